// round 10
// baseline (speedup 1.0000x reference)
#include <cuda_runtime.h>
#include <cuda_bf16.h>

// position_encoder: out[b,s,j] = x[b,s,j] + (j even ? sin : cos)(s / 10000^((j+1)/1024))
// B=4, S=8192, D=1024, fp32.
// Contiguous-segment design: block = 32KB contiguous span of ONE batch
// (8 rows x 1024 cols) -> 1 read stream + 1 write stream per block.
// 512 threads; thread owns col-group d4 at rows r, r+2, r+4, r+6:
// seed sincosf (fp64 theta) once, then 3 angle-additions by 2*fd (baked table).

#define PE_S     8192
#define PE_D     1024
#define PE_B     4
#define PE_ROWS  8                  // rows per block (one batch)
#define PE_D4    (PE_D / 4)         // 256 float4 per row
#define SEGS     (PE_S / PE_ROWS)   // 1024 segments per batch

struct PETab {
    double fd[PE_D];   // 10000^(-(j+1)/1024)
    float  s2[PE_D];   // sin(2*fd_j)
    float  c2[PE_D];   // cos(2*fd_j)
};

constexpr double cexp_small(double t) {
    double r = 1.0;
    for (int k = 24; k >= 1; --k) r = 1.0 + t * r / (double)k;
    return r;
}
constexpr double csin(double x) {
    double x2 = x * x, term = x, sum = x;
    for (int k = 1; k <= 12; ++k) { term *= -x2 / (double)((2 * k) * (2 * k + 1)); sum += term; }
    return sum;
}
constexpr double ccos(double x) {
    double x2 = x * x, term = 1.0, sum = 1.0;
    for (int k = 1; k <= 12; ++k) { term *= -x2 / (double)((2 * k - 1) * (2 * k)); sum += term; }
    return sum;
}
constexpr PETab make_tab() {
    PETab t{};
    const double kexp = 13.287712379549449 / 1024.0;  // log2(10000)/1024
    const double ln2  = 0.6931471805599453;
    for (int j = 0; j < PE_D; ++j) {
        const double e = (double)(j + 1) * kexp;
        const int    n = (int)e;
        const double f = e - (double)n;
        double v = cexp_small(-f * ln2);              // 2^-frac
        for (int i = 0; i < n; ++i) v *= 0.5;         // * 2^-int (exact)
        t.fd[j] = v;
        t.s2[j] = (float)csin(2.0 * v);
        t.c2[j] = (float)ccos(2.0 * v);
    }
    return t;
}
__device__ constexpr PETab g_tab = make_tab();

__global__ __launch_bounds__(512)
void position_encoder_kernel(const float4* __restrict__ x, float4* __restrict__ out) {
    const unsigned d4  = threadIdx.x & (PE_D4 - 1);   // column group 0..255
    const unsigned r   = threadIdx.x >> 8;            // row parity 0..1
    const unsigned b   = blockIdx.x >> 10;            // batch 0..3
    const unsigned seg = blockIdx.x & (SEGS - 1);     // segment within batch
    const unsigned s0  = seg * PE_ROWS + r;           // first row for this thread
    const unsigned j0  = d4 * 4;

    // seed at row s0 (fp64 theta -> accurate fp32 sincos)
    float sn[4], cs[4], sf[4], cf[4];
#pragma unroll
    for (int c = 0; c < 4; c++) {
        sincosf((float)((double)s0 * g_tab.fd[j0 + c]), &sn[c], &cs[c]);
        sf[c] = g_tab.s2[j0 + c];                     // step = 2*fd (rows stride 2)
        cf[c] = g_tab.c2[j0 + c];
    }

    // pos vectors for rows s0, s0+2, s0+4, s0+6 via angle addition
    float4 p[4];
#pragma unroll
    for (int k = 0; k < 4; k++) {
        p[k] = make_float4(sn[0], cs[1], sn[2], cs[3]);
        if (k < 3) {
#pragma unroll
            for (int c = 0; c < 4; c++) {
                const float ns = fmaf(sn[c], cf[c],  cs[c] * sf[c]);
                const float nc = fmaf(cs[c], cf[c], -sn[c] * sf[c]);
                sn[c] = ns; cs[c] = nc;
            }
        }
    }

    // contiguous 32KB span: base float4 index of this thread's first element
    const unsigned base = (b * (unsigned)PE_S + s0) * PE_D4 + d4;
    const unsigned step = 2u * PE_D4;                 // 2 rows = 512 float4

    // front-batch all 4 loads, add, store
    float4 v[4];
#pragma unroll
    for (int k = 0; k < 4; k++) v[k] = x[base + (unsigned)k * step];
#pragma unroll
    for (int k = 0; k < 4; k++) {
        v[k].x += p[k].x; v[k].y += p[k].y; v[k].z += p[k].z; v[k].w += p[k].w;
    }
#pragma unroll
    for (int k = 0; k < 4; k++) out[base + (unsigned)k * step] = v[k];
}

extern "C" void kernel_launch(void* const* d_in, const int* in_sizes, int n_in,
                              void* d_out, int out_size) {
    (void)in_sizes; (void)n_in; (void)out_size;
    const float4* x = (const float4*)d_in[0];
    float4* out = (float4*)d_out;
    position_encoder_kernel<<<PE_B * SEGS, 512>>>(x, out);
}

// round 11
// speedup vs baseline: 1.0457x; 1.0457x over previous
#include <cuda_runtime.h>
#include <cuda_bf16.h>

// position_encoder: out[b,s,j] = x[b,s,j] + (j even ? sin : cos)(s / 10000^((j+1)/1024))
// B=4, S=8192, D=1024, fp32.
// Best-bench design (R8) + explicit register budget: 512-thread blocks,
// 2 rows/block (thread = row x col4), direct per-row sincosf seeding from
// fp64 theta, 4 batch loads front-batched (fits in regs), 4 adds, 4 stores.
// __launch_bounds__(512,3) -> up to 42 regs at the same 3 blocks/SM.

#define PE_S     8192
#define PE_D     1024
#define PE_B     4
#define PE_ROWS  2                 // rows per block
#define PE_D4    (PE_D / 4)        // 256 float4 per row

struct PETab { double fd[PE_D]; };

constexpr double cexp_small(double t) {
    double r = 1.0;
    for (int k = 24; k >= 1; --k) r = 1.0 + t * r / (double)k;
    return r;
}
constexpr PETab make_tab() {
    PETab t{};
    const double kexp = 13.287712379549449 / 1024.0;  // log2(10000)/1024
    const double ln2  = 0.6931471805599453;
    for (int j = 0; j < PE_D; ++j) {
        const double e = (double)(j + 1) * kexp;
        const int    n = (int)e;
        const double f = e - (double)n;
        double v = cexp_small(-f * ln2);              // 2^-frac
        for (int i = 0; i < n; ++i) v *= 0.5;         // * 2^-int (exact)
        t.fd[j] = v;
    }
    return t;
}
__device__ constexpr PETab g_tab = make_tab();

__global__ __launch_bounds__(512, 3)
void position_encoder_kernel(const float4* __restrict__ x, float4* __restrict__ out) {
    const unsigned d4 = threadIdx.x & (PE_D4 - 1);    // 0..255 -> column group
    const unsigned r  = threadIdx.x >> 8;             // 0..1   -> row within block
    const unsigned s  = blockIdx.x * PE_ROWS + r;     // global row
    const unsigned j0 = d4 * 4;

    // pos vector for (s, j0..j0+3): fp64 theta -> accurate fp32 sincos
    float sn[4], cs[4];
#pragma unroll
    for (int c = 0; c < 4; c++)
        sincosf((float)((double)s * g_tab.fd[j0 + c]), &sn[c], &cs[c]);
    const float4 p = make_float4(sn[0], cs[1], sn[2], cs[3]);

    const unsigned bstride = (unsigned)PE_S * PE_D4;  // float4 per batch
    const unsigned base    = s * PE_D4 + d4;
    const float4* __restrict__ xp = x   + base;
    float4* __restrict__       op = out + base;

    // front-batch the 4 batch loads, then add, then store
    float4 v[PE_B];
#pragma unroll
    for (int b = 0; b < PE_B; b++) v[b] = xp[(size_t)b * bstride];
#pragma unroll
    for (int b = 0; b < PE_B; b++) {
        v[b].x += p.x; v[b].y += p.y; v[b].z += p.z; v[b].w += p.w;
    }
#pragma unroll
    for (int b = 0; b < PE_B; b++) op[(size_t)b * bstride] = v[b];
}

extern "C" void kernel_launch(void* const* d_in, const int* in_sizes, int n_in,
                              void* d_out, int out_size) {
    (void)in_sizes; (void)n_in; (void)out_size;
    const float4* x = (const float4*)d_in[0];
    float4* out = (float4*)d_out;
    position_encoder_kernel<<<PE_S / PE_ROWS, 512>>>(x, out);
}